// round 6
// baseline (speedup 1.0000x reference)
#include <cuda_runtime.h>
#include <cuda_bf16.h>
#include <cstdint>

#define BATCH 2
#define CCH   512
#define SSP   2304
#define NH    8
#define HD    64
#define CPG   16
#define EPSV  1e-5f
// softmax scale with log2(e) folded in: attention computed in log2 domain
#define QSC   (0.044194173824159216f * 1.4426950408889634f)

typedef __nv_bfloat16 bf16;

// Scratch (allocation-free rule: __device__ globals) — bf16 intermediates
__device__ bf16 g_norm[BATCH * CCH * SSP];
__device__ bf16 g_qkv [BATCH * 3 * CCH * SSP];
__device__ bf16 g_att [BATCH * CCH * SSP];
__device__ bf16 g_wqb [3 * CCH * CCH];
__device__ bf16 g_wob [CCH * CCH];

// ---------------------------------------------------------------------------
// PTX helpers
// ---------------------------------------------------------------------------
__device__ __forceinline__ unsigned sptr(const void* p) {
    return (unsigned)__cvta_generic_to_shared(p);
}
__device__ __forceinline__ void ldsm_x4(unsigned r[4], unsigned a) {
    asm volatile("ldmatrix.sync.aligned.m8n8.x4.shared.b16 {%0,%1,%2,%3}, [%4];"
                 : "=r"(r[0]), "=r"(r[1]), "=r"(r[2]), "=r"(r[3]) : "r"(a));
}
__device__ __forceinline__ void ldsm_x4t(unsigned r[4], unsigned a) {
    asm volatile("ldmatrix.sync.aligned.m8n8.x4.trans.shared.b16 {%0,%1,%2,%3}, [%4];"
                 : "=r"(r[0]), "=r"(r[1]), "=r"(r[2]), "=r"(r[3]) : "r"(a));
}
__device__ __forceinline__ void mma_bf16(float d[4], const unsigned a[4],
                                         const unsigned b[2], const float c[4]) {
    asm volatile(
        "mma.sync.aligned.m16n8k16.row.col.f32.bf16.bf16.f32 "
        "{%0,%1,%2,%3}, {%4,%5,%6,%7}, {%8,%9}, {%10,%11,%12,%13};\n"
        : "=f"(d[0]), "=f"(d[1]), "=f"(d[2]), "=f"(d[3])
        : "r"(a[0]), "r"(a[1]), "r"(a[2]), "r"(a[3]), "r"(b[0]), "r"(b[1]),
          "f"(c[0]), "f"(c[1]), "f"(c[2]), "f"(c[3]));
}
__device__ __forceinline__ float ex2(float x) {
    float y;
    asm("ex2.approx.f32 %0, %1;" : "=f"(y) : "f"(x));
    return y;
}
#define CP16(dst, src) \
    asm volatile("cp.async.cg.shared.global [%0], [%1], 16;" :: "r"(dst), "l"(src) : "memory")
#define CP_COMMIT() asm volatile("cp.async.commit_group;" ::: "memory")
#define CP_WAIT1()  asm volatile("cp.async.wait_group 1;" ::: "memory")
#define CP_WAIT0()  asm volatile("cp.async.wait_group 0;" ::: "memory")

__device__ __forceinline__ bf16 tob(float f) { return __float2bfloat16_rn(f); }

// ---------------------------------------------------------------------------
// Weight conversion fp32 -> bf16
// ---------------------------------------------------------------------------
__global__ void wconv_kernel(const float* __restrict__ wq,
                             const float* __restrict__ wo) {
    int t = blockIdx.x * 256 + threadIdx.x;
    const int n1 = 3 * CCH * CCH / 4;
    const int n2 = CCH * CCH / 4;
    if (t < n1) {
        float4 v = ((const float4*)wq)[t];
        bf16* o = g_wqb + t * 4;
        o[0] = tob(v.x); o[1] = tob(v.y); o[2] = tob(v.z); o[3] = tob(v.w);
    } else if (t < n1 + n2) {
        int u = t - n1;
        float4 v = ((const float4*)wo)[u];
        bf16* o = g_wob + u * 4;
        o[0] = tob(v.x); o[1] = tob(v.y); o[2] = tob(v.z); o[3] = tob(v.w);
    }
}

// ---------------------------------------------------------------------------
// GroupNorm -> bf16
// ---------------------------------------------------------------------------
__global__ void gn_kernel(const float* __restrict__ x,
                          const float* __restrict__ gamma,
                          const float* __restrict__ beta) {
    int b = blockIdx.x >> 5;
    int g = blockIdx.x & 31;
    const float4* xp = (const float4*)(x + (size_t)(b * CCH + g * CPG) * SSP);
    bf16* op = g_norm + (size_t)(b * CCH + g * CPG) * SSP;
    int tid = threadIdx.x;
    const int n4 = CPG * SSP / 4;  // 9216

    float s0 = 0.f, s1 = 0.f;
    for (int i = tid; i < n4; i += 256) {
        float4 v = xp[i];
        s0 += v.x + v.y + v.z + v.w;
        s1 += v.x * v.x + v.y * v.y + v.z * v.z + v.w * v.w;
    }
#pragma unroll
    for (int o = 16; o > 0; o >>= 1) {
        s0 += __shfl_xor_sync(0xffffffffu, s0, o);
        s1 += __shfl_xor_sync(0xffffffffu, s1, o);
    }
    __shared__ float sm0[8], sm1[8], stat[2];
    int w = tid >> 5;
    if ((tid & 31) == 0) { sm0[w] = s0; sm1[w] = s1; }
    __syncthreads();
    if (tid == 0) {
        float a = 0.f, q = 0.f;
#pragma unroll
        for (int i = 0; i < 8; i++) { a += sm0[i]; q += sm1[i]; }
        float mean = a * (1.f / 36864.f);
        float var  = q * (1.f / 36864.f) - mean * mean;
        stat[0] = mean;
        stat[1] = rsqrtf(var + EPSV);
    }
    __syncthreads();
    float mean = stat[0], rstd = stat[1];
    for (int i = tid; i < n4; i += 256) {
        int c = g * CPG + i / 576;
        float ga = gamma[c] * rstd;
        float be = beta[c] - mean * ga;
        float4 v = xp[i];
        bf16 o4[4];
        o4[0] = tob(v.x * ga + be); o4[1] = tob(v.y * ga + be);
        o4[2] = tob(v.z * ga + be); o4[3] = tob(v.w * ga + be);
        *(uint2*)(op + i * 4) = *(uint2*)o4;
    }
}

// ---------------------------------------------------------------------------
// bf16 tensor-core GEMM: C[M,N] = A[M,K] @ B[K,N]. 128x128 tile, ktile 32,
// 256 thr = 8 warps (2Mx4N), warp 64x32. cp.async 2-stage double buffer.
// qscale: rows with (m%192)<64 scaled by QSC (Q rows; folds softmax scale
// and log2e into Q).
// ---------------------------------------------------------------------------
#define AST 40
#define BST 136

__device__ __forceinline__ void gemm_core(
    int M, int N, int K,
    const bf16* __restrict__ A, const bf16* __restrict__ Bp,
    bf16* __restrict__ Cb, float* __restrict__ Cf,
    const float* __restrict__ bias, const float* __restrict__ res,
    bool qscale) {
    __shared__ bf16 As[2][128 * AST];
    __shared__ bf16 Bs[2][32 * BST];
    int tid = threadIdx.x;
    int lane = tid & 31, wid = tid >> 5;
    int wm = (wid >> 2) * 64, wn = (wid & 3) * 32;
    int m0 = blockIdx.y * 128, n0 = blockIdx.x * 128;
    int r0 = lane >> 2, c2 = lane & 3;

    int lm = tid >> 2, lko = (tid & 3) * 8;
    int lk = tid >> 4, lno = (tid & 15) * 8;

    const bf16* Ag = A + (size_t)(m0 + lm) * K + lko;
    const bf16* Bg = Bp + (size_t)lk * N + n0 + lno;

    int a_m = ((lane >> 3) & 1) * 8 + (lane & 7);
    int a_k = ((lane >> 4) & 1) * 8;
    int b_k = ((lane >> 3) & 1) * 8 + (lane & 7);
    int b_n = ((lane >> 4) & 1) * 8;

    float acc[4][4][4];
#pragma unroll
    for (int mt = 0; mt < 4; mt++)
#pragma unroll
        for (int nt = 0; nt < 4; nt++)
#pragma unroll
            for (int e = 0; e < 4; e++) acc[mt][nt][e] = 0.f;

    int nkt = K >> 5;
#pragma unroll
    for (int r = 0; r < 2; r++) {
        CP16(sptr(&As[0][(lm + r * 64) * AST + lko]), Ag + (size_t)r * 64 * K);
        CP16(sptr(&Bs[0][(lk + r * 16) * BST + lno]), Bg + (size_t)r * 16 * N);
    }
    CP_COMMIT();

    for (int kt = 0; kt < nkt; kt++) {
        int buf = kt & 1;
        if (kt + 1 < nkt) {
            int nb = buf ^ 1;
#pragma unroll
            for (int r = 0; r < 2; r++) {
                CP16(sptr(&As[nb][(lm + r * 64) * AST + lko]),
                     Ag + (size_t)(kt + 1) * 32 + (size_t)r * 64 * K);
                CP16(sptr(&Bs[nb][(lk + r * 16) * BST + lno]),
                     Bg + (size_t)((kt + 1) * 32 + r * 16) * N);
            }
            CP_COMMIT();
            CP_WAIT1();
        } else {
            CP_WAIT0();
        }
        __syncthreads();

#pragma unroll
        for (int ks = 0; ks < 2; ks++) {
            unsigned af[4][4], bf_[2][4];
#pragma unroll
            for (int mt = 0; mt < 4; mt++)
                ldsm_x4(af[mt], sptr(&As[buf][(wm + mt * 16 + a_m) * AST + ks * 16 + a_k]));
#pragma unroll
            for (int ng = 0; ng < 2; ng++)
                ldsm_x4t(bf_[ng], sptr(&Bs[buf][(ks * 16 + b_k) * BST + wn + ng * 16 + b_n]));
#pragma unroll
            for (int mt = 0; mt < 4; mt++)
#pragma unroll
                for (int nt = 0; nt < 4; nt++)
                    mma_bf16(acc[mt][nt], af[mt], &bf_[nt >> 1][(nt & 1) * 2], acc[mt][nt]);
        }
        __syncthreads();
    }

#pragma unroll
    for (int mt = 0; mt < 4; mt++) {
        int mA = m0 + wm + mt * 16 + r0;
        float f0 = 1.f, f1 = 1.f;
        if (qscale) {
            f0 = ((mA % 192) < 64) ? QSC : 1.f;
            f1 = (((mA + 8) % 192) < 64) ? QSC : 1.f;
        }
#pragma unroll
        for (int nt = 0; nt < 4; nt++) {
            int n = n0 + wn + nt * 8 + 2 * c2;
            if (Cb) {
                bf16 p0[2] = {tob(acc[mt][nt][0] * f0), tob(acc[mt][nt][1] * f0)};
                bf16 p1[2] = {tob(acc[mt][nt][2] * f1), tob(acc[mt][nt][3] * f1)};
                *(unsigned*)(Cb + (size_t)mA * N + n) = *(unsigned*)p0;
                *(unsigned*)(Cb + (size_t)(mA + 8) * N + n) = *(unsigned*)p1;
            } else {
                float bv0 = bias[mA], bv1 = bias[mA + 8];
                float2 o0, o1;
                o0.x = acc[mt][nt][0] + bv0; o0.y = acc[mt][nt][1] + bv0;
                o1.x = acc[mt][nt][2] + bv1; o1.y = acc[mt][nt][3] + bv1;
                float2 q0v = *(const float2*)(res + (size_t)mA * N + n);
                float2 q1v = *(const float2*)(res + (size_t)(mA + 8) * N + n);
                o0.x += q0v.x; o0.y += q0v.y; o1.x += q1v.x; o1.y += q1v.y;
                *(float2*)(Cf + (size_t)mA * N + n) = o0;
                *(float2*)(Cf + (size_t)(mA + 8) * N + n) = o1;
            }
        }
    }
}

__global__ void __launch_bounds__(256, 2) qkv_gemm_kernel() {
    int b = blockIdx.z;
    gemm_core(3 * CCH, SSP, CCH, g_wqb,
              g_norm + (size_t)b * CCH * SSP,
              g_qkv + (size_t)b * 3 * CCH * SSP, nullptr,
              nullptr, nullptr, true);
}

__global__ void __launch_bounds__(256, 2) out_gemm_kernel(const float* __restrict__ b_out,
                                                          const float* __restrict__ x,
                                                          float* __restrict__ out) {
    int b = blockIdx.z;
    gemm_core(CCH, SSP, CCH, g_wob,
              g_att + (size_t)b * CCH * SSP,
              nullptr, out + (size_t)b * CCH * SSP,
              b_out, x + (size_t)b * CCH * SSP, false);
}

// ---------------------------------------------------------------------------
// Flash attention bf16, log2-domain softmax, interleaved exp/PV.
// Block = 128 queries of one (b,h), 256 threads = 8 warps. K/V cp.async
// double-buffered. Q pre-scaled by QSC (folded in qkv epilogue).
// ---------------------------------------------------------------------------
#define QST 136
#define KST 72
#define NT_TILES (SSP / 64)

__global__ void __launch_bounds__(256, 2) attn_kernel() {
    extern __shared__ bf16 smn[];
    bf16* Qs = smn;                       // 64*136
    bf16* Ks = Qs + 64 * QST;             // 2*64*72
    bf16* Vs = Ks + 2 * 64 * KST;         // 2*64*72
    bf16* Ps = Vs + 2 * 64 * KST;         // 128*72

    int tid = threadIdx.x, lane = tid & 31, w = tid >> 5;
    int r0 = lane >> 2, c2 = lane & 3;
    int wm = w * 16;
    int h = blockIdx.y, b = blockIdx.z;
    int q0 = blockIdx.x * 128;
    const bf16* qp = g_qkv + ((size_t)b * 3 * CCH + h * 3 * HD) * SSP;
    const bf16* kp = qp + (size_t)HD * SSP;
    const bf16* vp = qp + (size_t)2 * HD * SSP;

    int t8  = (lane >> 3) & 1, t16 = (lane >> 4) & 1, t7 = lane & 7;

    // Load Q tile [d][i]
    {
        int io = (tid & 15) * 8, d = tid >> 4;
#pragma unroll
        for (int r = 0; r < 4; r++)
            *(uint4*)(Qs + (d + 16 * r) * QST + io) =
                *(const uint4*)(qp + (size_t)(d + 16 * r) * SSP + q0 + io);
    }

    int ld = tid >> 3, ljo = (tid & 7) * 8;
#pragma unroll
    for (int r = 0; r < 2; r++) {
        CP16(sptr(Ks + (ld + 32 * r) * KST + ljo), kp + (size_t)(ld + 32 * r) * SSP + ljo);
        CP16(sptr(Vs + (ld + 32 * r) * KST + ljo), vp + (size_t)(ld + 32 * r) * SSP + ljo);
    }
    CP_COMMIT();

    float m_run[2] = {-1e30f, -1e30f}, l_run[2] = {0.f, 0.f};
    float o[8][4];
#pragma unroll
    for (int nt = 0; nt < 8; nt++)
#pragma unroll
        for (int e = 0; e < 4; e++) o[nt][e] = 0.f;

    for (int t = 0; t < NT_TILES; t++) {
        int buf = t & 1;
        if (t + 1 < NT_TILES) {
            int nb = buf ^ 1;
            int t0n = (t + 1) * 64;
#pragma unroll
            for (int r = 0; r < 2; r++) {
                CP16(sptr(Ks + (nb * 64 + ld + 32 * r) * KST + ljo),
                     kp + (size_t)(ld + 32 * r) * SSP + t0n + ljo);
                CP16(sptr(Vs + (nb * 64 + ld + 32 * r) * KST + ljo),
                     vp + (size_t)(ld + 32 * r) * SSP + t0n + ljo);
            }
            CP_COMMIT();
            CP_WAIT1();
        } else {
            CP_WAIT0();
        }
        __syncthreads();

        // ---- S = Q^T K (log2-domain scores)
        float s[8][4];
#pragma unroll
        for (int nt = 0; nt < 8; nt++)
#pragma unroll
            for (int e = 0; e < 4; e++) s[nt][e] = 0.f;
        const bf16* Kb = Ks + buf * 64 * KST;
#pragma unroll
        for (int ks = 0; ks < 4; ks++) {
            unsigned a[4], bb[4][4];
            ldsm_x4t(a, sptr(Qs + (ks * 16 + t16 * 8 + t7) * QST + wm + t8 * 8));
#pragma unroll
            for (int ng = 0; ng < 4; ng++)
                ldsm_x4t(bb[ng], sptr(Kb + (ks * 16 + t8 * 8 + t7) * KST + ng * 16 + t16 * 8));
#pragma unroll
            for (int nt = 0; nt < 8; nt++)
                mma_bf16(s[nt], a, &bb[nt >> 1][(nt & 1) * 2], s[nt]);
        }

        // ---- row max (quad reduction)
        float mx0 = -1e30f, mx1 = -1e30f;
#pragma unroll
        for (int nt = 0; nt < 8; nt++) {
            mx0 = fmaxf(mx0, fmaxf(s[nt][0], s[nt][1]));
            mx1 = fmaxf(mx1, fmaxf(s[nt][2], s[nt][3]));
        }
#pragma unroll
        for (int off = 1; off <= 2; off <<= 1) {
            mx0 = fmaxf(mx0, __shfl_xor_sync(0xffffffffu, mx0, off));
            mx1 = fmaxf(mx1, __shfl_xor_sync(0xffffffffu, mx1, off));
        }
        float mn0 = fmaxf(m_run[0], mx0), mn1 = fmaxf(m_run[1], mx1);
        float cr0 = ex2(m_run[0] - mn0), cr1 = ex2(m_run[1] - mn1);
        m_run[0] = mn0; m_run[1] = mn1;
#pragma unroll
        for (int nt = 0; nt < 8; nt++) {
            o[nt][0] *= cr0; o[nt][1] *= cr0;
            o[nt][2] *= cr1; o[nt][3] *= cr1;
        }

        // ---- interleaved: exp2 chunk of P, then PV mma for that k-chunk
        float sum0 = 0.f, sum1 = 0.f;
        const bf16* Vb = Vs + buf * 64 * KST;
#pragma unroll
        for (int ks = 0; ks < 4; ks++) {
#pragma unroll
            for (int u = 0; u < 2; u++) {
                int nt = ks * 2 + u;
                s[nt][0] = ex2(s[nt][0] - mn0);
                s[nt][1] = ex2(s[nt][1] - mn0);
                s[nt][2] = ex2(s[nt][2] - mn1);
                s[nt][3] = ex2(s[nt][3] - mn1);
                sum0 += s[nt][0] + s[nt][1];
                sum1 += s[nt][2] + s[nt][3];
                bf16 p0[2] = {tob(s[nt][0]), tob(s[nt][1])};
                bf16 p1[2] = {tob(s[nt][2]), tob(s[nt][3])};
                *(unsigned*)(Ps + (wm + r0) * KST + nt * 8 + 2 * c2) = *(unsigned*)p0;
                *(unsigned*)(Ps + (wm + r0 + 8) * KST + nt * 8 + 2 * c2) = *(unsigned*)p1;
            }
            __syncwarp();
            unsigned a[4], bb[4][4];
            ldsm_x4(a, sptr(Ps + (wm + t8 * 8 + t7) * KST + ks * 16 + t16 * 8));
#pragma unroll
            for (int ng = 0; ng < 4; ng++)
                ldsm_x4(bb[ng], sptr(Vb + (ng * 16 + t16 * 8 + t7) * KST + ks * 16 + t8 * 8));
#pragma unroll
            for (int nd = 0; nd < 8; nd++)
                mma_bf16(o[nd], a, &bb[nd >> 1][(nd & 1) * 2], o[nd]);
        }

#pragma unroll
        for (int off = 1; off <= 2; off <<= 1) {
            sum0 += __shfl_xor_sync(0xffffffffu, sum0, off);
            sum1 += __shfl_xor_sync(0xffffffffu, sum1, off);
        }
        l_run[0] = l_run[0] * cr0 + sum0;
        l_run[1] = l_run[1] * cr1 + sum1;
        __syncthreads();
    }

    // ---- finalize
    float inv0 = 1.f / l_run[0], inv1 = 1.f / l_run[1];
    bf16* Os = Qs;
#pragma unroll
    for (int nt = 0; nt < 8; nt++) {
        int dd = nt * 8 + 2 * c2;
        Os[dd * QST + wm + r0]           = tob(o[nt][0] * inv0);
        Os[(dd + 1) * QST + wm + r0]     = tob(o[nt][1] * inv0);
        Os[dd * QST + wm + r0 + 8]       = tob(o[nt][2] * inv1);
        Os[(dd + 1) * QST + wm + r0 + 8] = tob(o[nt][3] * inv1);
    }
    __syncthreads();
    bf16* ap = g_att + ((size_t)b * CCH + h * HD) * SSP;
    {
        int io = (tid & 15) * 8, d = tid >> 4;
#pragma unroll
        for (int r = 0; r < 4; r++)
            *(uint4*)(ap + (size_t)(d + 16 * r) * SSP + q0 + io) =
                *(uint4*)(Os + (d + 16 * r) * QST + io);
    }
}

// ---------------------------------------------------------------------------
extern "C" void kernel_launch(void* const* d_in, const int* in_sizes, int n_in,
                              void* d_out, int out_size) {
    const float* x     = (const float*)d_in[0];
    const float* gamma = (const float*)d_in[1];
    const float* beta  = (const float*)d_in[2];
    const float* w_qkv = (const float*)d_in[3];
    const float* w_out = (const float*)d_in[4];
    const float* b_out = (const float*)d_in[5];
    float* out = (float*)d_out;

    const int attn_smem = (64 * QST + 4 * 64 * KST + 128 * KST) * (int)sizeof(bf16);
    cudaFuncSetAttribute(attn_kernel, cudaFuncAttributeMaxDynamicSharedMemorySize,
                         attn_smem);

    wconv_kernel<<<1024, 256>>>(w_qkv, w_out);
    gn_kernel<<<BATCH * 32, 256>>>(x, gamma, beta);
    qkv_gemm_kernel<<<dim3(SSP / 128, 3 * CCH / 128, BATCH), 256>>>();
    attn_kernel<<<dim3(SSP / 128, NH, BATCH), 256, attn_smem>>>();
    out_gemm_kernel<<<dim3(SSP / 128, CCH / 128, BATCH), 256>>>(b_out, x, out);
}

// round 8
// speedup vs baseline: 1.0451x; 1.0451x over previous
#include <cuda_runtime.h>
#include <cuda_bf16.h>
#include <cstdint>

#define BATCH 2
#define CCH   512
#define SSP   2304
#define NH    8
#define HD    64
#define CPG   16
#define EPSV  1e-5f
// softmax scale with log2(e) folded in: attention computed in log2 domain
#define QSC   (0.044194173824159216f * 1.4426950408889634f)

typedef __nv_bfloat16 bf16;

// Scratch (allocation-free rule: __device__ globals) — bf16 intermediates
__device__ bf16 g_norm[BATCH * CCH * SSP];
__device__ bf16 g_qkv [BATCH * 3 * CCH * SSP];
__device__ bf16 g_att [BATCH * CCH * SSP];
__device__ bf16 g_wqb [3 * CCH * CCH];
__device__ bf16 g_wob [CCH * CCH];

// ---------------------------------------------------------------------------
// PTX helpers
// ---------------------------------------------------------------------------
__device__ __forceinline__ unsigned sptr(const void* p) {
    return (unsigned)__cvta_generic_to_shared(p);
}
__device__ __forceinline__ void ldsm_x4(unsigned r[4], unsigned a) {
    asm volatile("ldmatrix.sync.aligned.m8n8.x4.shared.b16 {%0,%1,%2,%3}, [%4];"
                 : "=r"(r[0]), "=r"(r[1]), "=r"(r[2]), "=r"(r[3]) : "r"(a));
}
__device__ __forceinline__ void ldsm_x4t(unsigned r[4], unsigned a) {
    asm volatile("ldmatrix.sync.aligned.m8n8.x4.trans.shared.b16 {%0,%1,%2,%3}, [%4];"
                 : "=r"(r[0]), "=r"(r[1]), "=r"(r[2]), "=r"(r[3]) : "r"(a));
}
__device__ __forceinline__ void mma_bf16(float d[4], const unsigned a[4],
                                         const unsigned b[2], const float c[4]) {
    asm volatile(
        "mma.sync.aligned.m16n8k16.row.col.f32.bf16.bf16.f32 "
        "{%0,%1,%2,%3}, {%4,%5,%6,%7}, {%8,%9}, {%10,%11,%12,%13};\n"
        : "=f"(d[0]), "=f"(d[1]), "=f"(d[2]), "=f"(d[3])
        : "r"(a[0]), "r"(a[1]), "r"(a[2]), "r"(a[3]), "r"(b[0]), "r"(b[1]),
          "f"(c[0]), "f"(c[1]), "f"(c[2]), "f"(c[3]));
}
__device__ __forceinline__ float ex2(float x) {
    float y;
    asm("ex2.approx.f32 %0, %1;" : "=f"(y) : "f"(x));
    return y;
}
// pack two f32 -> bf16x2 register (lo = a, hi = b)
__device__ __forceinline__ unsigned pk2(float a, float b) {
    unsigned d;
    asm("cvt.rn.bf16x2.f32 %0, %1, %2;" : "=r"(d) : "f"(b), "f"(a));
    return d;
}
#define CP16(dst, src) \
    asm volatile("cp.async.cg.shared.global [%0], [%1], 16;" :: "r"(dst), "l"(src) : "memory")
#define CP_COMMIT() asm volatile("cp.async.commit_group;" ::: "memory")
#define CP_WAIT1()  asm volatile("cp.async.wait_group 1;" ::: "memory")
#define CP_WAIT0()  asm volatile("cp.async.wait_group 0;" ::: "memory")

__device__ __forceinline__ bf16 tob(float f) { return __float2bfloat16_rn(f); }

// ---------------------------------------------------------------------------
// Weight conversion fp32 -> bf16
// ---------------------------------------------------------------------------
__global__ void wconv_kernel(const float* __restrict__ wq,
                             const float* __restrict__ wo) {
    int t = blockIdx.x * 256 + threadIdx.x;
    const int n1 = 3 * CCH * CCH / 4;
    const int n2 = CCH * CCH / 4;
    if (t < n1) {
        float4 v = ((const float4*)wq)[t];
        bf16* o = g_wqb + t * 4;
        o[0] = tob(v.x); o[1] = tob(v.y); o[2] = tob(v.z); o[3] = tob(v.w);
    } else if (t < n1 + n2) {
        int u = t - n1;
        float4 v = ((const float4*)wo)[u];
        bf16* o = g_wob + u * 4;
        o[0] = tob(v.x); o[1] = tob(v.y); o[2] = tob(v.z); o[3] = tob(v.w);
    }
}

// ---------------------------------------------------------------------------
// GroupNorm -> bf16
// ---------------------------------------------------------------------------
__global__ void gn_kernel(const float* __restrict__ x,
                          const float* __restrict__ gamma,
                          const float* __restrict__ beta) {
    int b = blockIdx.x >> 5;
    int g = blockIdx.x & 31;
    const float4* xp = (const float4*)(x + (size_t)(b * CCH + g * CPG) * SSP);
    bf16* op = g_norm + (size_t)(b * CCH + g * CPG) * SSP;
    int tid = threadIdx.x;
    const int n4 = CPG * SSP / 4;  // 9216

    float s0 = 0.f, s1 = 0.f;
    for (int i = tid; i < n4; i += 256) {
        float4 v = xp[i];
        s0 += v.x + v.y + v.z + v.w;
        s1 += v.x * v.x + v.y * v.y + v.z * v.z + v.w * v.w;
    }
#pragma unroll
    for (int o = 16; o > 0; o >>= 1) {
        s0 += __shfl_xor_sync(0xffffffffu, s0, o);
        s1 += __shfl_xor_sync(0xffffffffu, s1, o);
    }
    __shared__ float sm0[8], sm1[8], stat[2];
    int w = tid >> 5;
    if ((tid & 31) == 0) { sm0[w] = s0; sm1[w] = s1; }
    __syncthreads();
    if (tid == 0) {
        float a = 0.f, q = 0.f;
#pragma unroll
        for (int i = 0; i < 8; i++) { a += sm0[i]; q += sm1[i]; }
        float mean = a * (1.f / 36864.f);
        float var  = q * (1.f / 36864.f) - mean * mean;
        stat[0] = mean;
        stat[1] = rsqrtf(var + EPSV);
    }
    __syncthreads();
    float mean = stat[0], rstd = stat[1];
    for (int i = tid; i < n4; i += 256) {
        int c = g * CPG + i / 576;
        float ga = gamma[c] * rstd;
        float be = beta[c] - mean * ga;
        float4 v = xp[i];
        bf16 o4[4];
        o4[0] = tob(v.x * ga + be); o4[1] = tob(v.y * ga + be);
        o4[2] = tob(v.z * ga + be); o4[3] = tob(v.w * ga + be);
        *(uint2*)(op + i * 4) = *(uint2*)o4;
    }
}

// ---------------------------------------------------------------------------
// bf16 tensor-core GEMM: C[M,N] = A[M,K] @ B[K,N]. 128x128 tile, ktile 32,
// 256 thr = 8 warps (2Mx4N), warp 64x32. cp.async 2-stage double buffer.
// ---------------------------------------------------------------------------
#define AST 40
#define BST 136

__device__ __forceinline__ void gemm_core(
    int M, int N, int K,
    const bf16* __restrict__ A, const bf16* __restrict__ Bp,
    bf16* __restrict__ Cb, float* __restrict__ Cf,
    const float* __restrict__ bias, const float* __restrict__ res,
    bool qscale) {
    __shared__ bf16 As[2][128 * AST];
    __shared__ bf16 Bs[2][32 * BST];
    int tid = threadIdx.x;
    int lane = tid & 31, wid = tid >> 5;
    int wm = (wid >> 2) * 64, wn = (wid & 3) * 32;
    int m0 = blockIdx.y * 128, n0 = blockIdx.x * 128;
    int r0 = lane >> 2, c2 = lane & 3;

    int lm = tid >> 2, lko = (tid & 3) * 8;
    int lk = tid >> 4, lno = (tid & 15) * 8;

    const bf16* Ag = A + (size_t)(m0 + lm) * K + lko;
    const bf16* Bg = Bp + (size_t)lk * N + n0 + lno;

    int a_m = ((lane >> 3) & 1) * 8 + (lane & 7);
    int a_k = ((lane >> 4) & 1) * 8;
    int b_k = ((lane >> 3) & 1) * 8 + (lane & 7);
    int b_n = ((lane >> 4) & 1) * 8;

    float acc[4][4][4];
#pragma unroll
    for (int mt = 0; mt < 4; mt++)
#pragma unroll
        for (int nt = 0; nt < 4; nt++)
#pragma unroll
            for (int e = 0; e < 4; e++) acc[mt][nt][e] = 0.f;

    int nkt = K >> 5;
#pragma unroll
    for (int r = 0; r < 2; r++) {
        CP16(sptr(&As[0][(lm + r * 64) * AST + lko]), Ag + (size_t)r * 64 * K);
        CP16(sptr(&Bs[0][(lk + r * 16) * BST + lno]), Bg + (size_t)r * 16 * N);
    }
    CP_COMMIT();

    for (int kt = 0; kt < nkt; kt++) {
        int buf = kt & 1;
        if (kt + 1 < nkt) {
            int nb = buf ^ 1;
#pragma unroll
            for (int r = 0; r < 2; r++) {
                CP16(sptr(&As[nb][(lm + r * 64) * AST + lko]),
                     Ag + (size_t)(kt + 1) * 32 + (size_t)r * 64 * K);
                CP16(sptr(&Bs[nb][(lk + r * 16) * BST + lno]),
                     Bg + (size_t)((kt + 1) * 32 + r * 16) * N);
            }
            CP_COMMIT();
            CP_WAIT1();
        } else {
            CP_WAIT0();
        }
        __syncthreads();

#pragma unroll
        for (int ks = 0; ks < 2; ks++) {
            unsigned af[4][4], bf_[2][4];
#pragma unroll
            for (int mt = 0; mt < 4; mt++)
                ldsm_x4(af[mt], sptr(&As[buf][(wm + mt * 16 + a_m) * AST + ks * 16 + a_k]));
#pragma unroll
            for (int ng = 0; ng < 2; ng++)
                ldsm_x4t(bf_[ng], sptr(&Bs[buf][(ks * 16 + b_k) * BST + wn + ng * 16 + b_n]));
#pragma unroll
            for (int mt = 0; mt < 4; mt++)
#pragma unroll
                for (int nt = 0; nt < 4; nt++)
                    mma_bf16(acc[mt][nt], af[mt], &bf_[nt >> 1][(nt & 1) * 2], acc[mt][nt]);
        }
        __syncthreads();
    }

#pragma unroll
    for (int mt = 0; mt < 4; mt++) {
        int mA = m0 + wm + mt * 16 + r0;
        float f0 = 1.f, f1 = 1.f;
        if (qscale) {
            f0 = ((mA % 192) < 64) ? QSC : 1.f;
            f1 = (((mA + 8) % 192) < 64) ? QSC : 1.f;
        }
#pragma unroll
        for (int nt = 0; nt < 4; nt++) {
            int n = n0 + wn + nt * 8 + 2 * c2;
            if (Cb) {
                unsigned p0 = pk2(acc[mt][nt][0] * f0, acc[mt][nt][1] * f0);
                unsigned p1 = pk2(acc[mt][nt][2] * f1, acc[mt][nt][3] * f1);
                *(unsigned*)(Cb + (size_t)mA * N + n) = p0;
                *(unsigned*)(Cb + (size_t)(mA + 8) * N + n) = p1;
            } else {
                float bv0 = bias[mA], bv1 = bias[mA + 8];
                float2 o0, o1;
                o0.x = acc[mt][nt][0] + bv0; o0.y = acc[mt][nt][1] + bv0;
                o1.x = acc[mt][nt][2] + bv1; o1.y = acc[mt][nt][3] + bv1;
                float2 q0v = *(const float2*)(res + (size_t)mA * N + n);
                float2 q1v = *(const float2*)(res + (size_t)(mA + 8) * N + n);
                o0.x += q0v.x; o0.y += q0v.y; o1.x += q1v.x; o1.y += q1v.y;
                *(float2*)(Cf + (size_t)mA * N + n) = o0;
                *(float2*)(Cf + (size_t)(mA + 8) * N + n) = o1;
            }
        }
    }
}

__global__ void __launch_bounds__(256, 2) qkv_gemm_kernel() {
    int b = blockIdx.z;
    gemm_core(3 * CCH, SSP, CCH, g_wqb,
              g_norm + (size_t)b * CCH * SSP,
              g_qkv + (size_t)b * 3 * CCH * SSP, nullptr,
              nullptr, nullptr, true);
}

__global__ void __launch_bounds__(256, 2) out_gemm_kernel(const float* __restrict__ b_out,
                                                          const float* __restrict__ x,
                                                          float* __restrict__ out) {
    int b = blockIdx.z;
    gemm_core(CCH, SSP, CCH, g_wob,
              g_att + (size_t)b * CCH * SSP,
              nullptr, out + (size_t)b * CCH * SSP,
              b_out, x + (size_t)b * CCH * SSP, false);
}

// ---------------------------------------------------------------------------
// Flash attention bf16, log2-domain softmax, P kept entirely in registers:
// the QK accumulator fragment IS the PV A-operand fragment (rows r0/r0+8,
// cols 2c2 within each 16-key chunk). No P SMEM, no STS/ldsm/syncwarp.
// Block = 128 queries of one (b,h), 256 threads = 8 warps. K/V cp.async
// double-buffered. Q pre-scaled by QSC (folded in qkv epilogue).
// ---------------------------------------------------------------------------
#define QST 136
#define KST 72
#define NT_TILES (SSP / 64)

__global__ void __launch_bounds__(256, 2) attn_kernel() {
    extern __shared__ bf16 smn[];
    bf16* Qs = smn;                       // 64*136
    bf16* Ks = Qs + 64 * QST;             // 2*64*72
    bf16* Vs = Ks + 2 * 64 * KST;         // 2*64*72

    int tid = threadIdx.x, lane = tid & 31, w = tid >> 5;
    int r0 = lane >> 2, c2 = lane & 3;
    int wm = w * 16;
    int h = blockIdx.y, b = blockIdx.z;
    int q0 = blockIdx.x * 128;
    const bf16* qp = g_qkv + ((size_t)b * 3 * CCH + h * 3 * HD) * SSP;
    const bf16* kp = qp + (size_t)HD * SSP;
    const bf16* vp = qp + (size_t)2 * HD * SSP;

    int t8  = (lane >> 3) & 1, t16 = (lane >> 4) & 1, t7 = lane & 7;

    // Load Q tile [d][i]
    {
        int io = (tid & 15) * 8, d = tid >> 4;
#pragma unroll
        for (int r = 0; r < 4; r++)
            *(uint4*)(Qs + (d + 16 * r) * QST + io) =
                *(const uint4*)(qp + (size_t)(d + 16 * r) * SSP + q0 + io);
    }

    int ld = tid >> 3, ljo = (tid & 7) * 8;
#pragma unroll
    for (int r = 0; r < 2; r++) {
        CP16(sptr(Ks + (ld + 32 * r) * KST + ljo), kp + (size_t)(ld + 32 * r) * SSP + ljo);
        CP16(sptr(Vs + (ld + 32 * r) * KST + ljo), vp + (size_t)(ld + 32 * r) * SSP + ljo);
    }
    CP_COMMIT();

    float m_run[2] = {-1e30f, -1e30f};
    float l_par[2] = {0.f, 0.f};  // per-lane partial sums; quad-reduced at end
    float o[8][4];
#pragma unroll
    for (int nt = 0; nt < 8; nt++)
#pragma unroll
        for (int e = 0; e < 4; e++) o[nt][e] = 0.f;

    for (int t = 0; t < NT_TILES; t++) {
        int buf = t & 1;
        if (t + 1 < NT_TILES) {
            int nb = buf ^ 1;
            int t0n = (t + 1) * 64;
#pragma unroll
            for (int r = 0; r < 2; r++) {
                CP16(sptr(Ks + (nb * 64 + ld + 32 * r) * KST + ljo),
                     kp + (size_t)(ld + 32 * r) * SSP + t0n + ljo);
                CP16(sptr(Vs + (nb * 64 + ld + 32 * r) * KST + ljo),
                     vp + (size_t)(ld + 32 * r) * SSP + t0n + ljo);
            }
            CP_COMMIT();
            CP_WAIT1();
        } else {
            CP_WAIT0();
        }
        __syncthreads();

        // ---- S = Q^T K (log2-domain scores)
        float s[8][4];
#pragma unroll
        for (int nt = 0; nt < 8; nt++)
#pragma unroll
            for (int e = 0; e < 4; e++) s[nt][e] = 0.f;
        const bf16* Kb = Ks + buf * 64 * KST;
#pragma unroll
        for (int ks = 0; ks < 4; ks++) {
            unsigned a[4], bb[4][4];
            ldsm_x4t(a, sptr(Qs + (ks * 16 + t16 * 8 + t7) * QST + wm + t8 * 8));
#pragma unroll
            for (int ng = 0; ng < 4; ng++)
                ldsm_x4t(bb[ng], sptr(Kb + (ks * 16 + t8 * 8 + t7) * KST + ng * 16 + t16 * 8));
#pragma unroll
            for (int nt = 0; nt < 8; nt++)
                mma_bf16(s[nt], a, &bb[nt >> 1][(nt & 1) * 2], s[nt]);
        }

        // ---- row max (quad reduction)
        float mx0 = -1e30f, mx1 = -1e30f;
#pragma unroll
        for (int nt = 0; nt < 8; nt++) {
            mx0 = fmaxf(mx0, fmaxf(s[nt][0], s[nt][1]));
            mx1 = fmaxf(mx1, fmaxf(s[nt][2], s[nt][3]));
        }
#pragma unroll
        for (int off = 1; off <= 2; off <<= 1) {
            mx0 = fmaxf(mx0, __shfl_xor_sync(0xffffffffu, mx0, off));
            mx1 = fmaxf(mx1, __shfl_xor_sync(0xffffffffu, mx1, off));
        }
        float mn0 = fmaxf(m_run[0], mx0), mn1 = fmaxf(m_run[1], mx1);
        float cr0 = ex2(m_run[0] - mn0), cr1 = ex2(m_run[1] - mn1);
        m_run[0] = mn0; m_run[1] = mn1;
#pragma unroll
        for (int nt = 0; nt < 8; nt++) {
            o[nt][0] *= cr0; o[nt][1] *= cr0;
            o[nt][2] *= cr1; o[nt][3] *= cr1;
        }

        // ---- exp2 in regs, pack P fragment directly, PV mma per k-chunk
        float sum0 = 0.f, sum1 = 0.f;
        const bf16* Vb = Vs + buf * 64 * KST;
#pragma unroll
        for (int ks = 0; ks < 4; ks++) {
            int n0i = 2 * ks, n1i = 2 * ks + 1;
            s[n0i][0] = ex2(s[n0i][0] - mn0);
            s[n0i][1] = ex2(s[n0i][1] - mn0);
            s[n0i][2] = ex2(s[n0i][2] - mn1);
            s[n0i][3] = ex2(s[n0i][3] - mn1);
            s[n1i][0] = ex2(s[n1i][0] - mn0);
            s[n1i][1] = ex2(s[n1i][1] - mn0);
            s[n1i][2] = ex2(s[n1i][2] - mn1);
            s[n1i][3] = ex2(s[n1i][3] - mn1);
            sum0 += s[n0i][0] + s[n0i][1] + s[n1i][0] + s[n1i][1];
            sum1 += s[n0i][2] + s[n0i][3] + s[n1i][2] + s[n1i][3];
            // A fragment for PV over keys ks*16..ks*16+15:
            // a0 = row r0 (keys +2c2), a1 = row r0+8, a2/a3 = keys +8+2c2.
            unsigned a[4];
            a[0] = pk2(s[n0i][0], s[n0i][1]);
            a[1] = pk2(s[n0i][2], s[n0i][3]);
            a[2] = pk2(s[n1i][0], s[n1i][1]);
            a[3] = pk2(s[n1i][2], s[n1i][3]);
            unsigned bb[4][4];
#pragma unroll
            for (int ng = 0; ng < 4; ng++)
                ldsm_x4(bb[ng], sptr(Vb + (ng * 16 + t16 * 8 + t7) * KST + ks * 16 + t8 * 8));
#pragma unroll
            for (int nd = 0; nd < 8; nd++)
                mma_bf16(o[nd], a, &bb[nd >> 1][(nd & 1) * 2], o[nd]);
        }
        l_par[0] = l_par[0] * cr0 + sum0;
        l_par[1] = l_par[1] * cr1 + sum1;
        __syncthreads();
    }

    // ---- final l reduction across quad, then finalize
    float l0 = l_par[0], l1 = l_par[1];
#pragma unroll
    for (int off = 1; off <= 2; off <<= 1) {
        l0 += __shfl_xor_sync(0xffffffffu, l0, off);
        l1 += __shfl_xor_sync(0xffffffffu, l1, off);
    }
    float inv0 = 1.f / l0, inv1 = 1.f / l1;
    bf16* Os = Qs;
#pragma unroll
    for (int nt = 0; nt < 8; nt++) {
        int dd = nt * 8 + 2 * c2;
        Os[dd * QST + wm + r0]           = tob(o[nt][0] * inv0);
        Os[(dd + 1) * QST + wm + r0]     = tob(o[nt][1] * inv0);
        Os[dd * QST + wm + r0 + 8]       = tob(o[nt][2] * inv1);
        Os[(dd + 1) * QST + wm + r0 + 8] = tob(o[nt][3] * inv1);
    }
    __syncthreads();
    bf16* ap = g_att + ((size_t)b * CCH + h * HD) * SSP;
    {
        int io = (tid & 15) * 8, d = tid >> 4;
#pragma unroll
        for (int r = 0; r < 4; r++)
            *(uint4*)(ap + (size_t)(d + 16 * r) * SSP + q0 + io) =
                *(uint4*)(Os + (d + 16 * r) * QST + io);
    }
}

// ---------------------------------------------------------------------------
extern "C" void kernel_launch(void* const* d_in, const int* in_sizes, int n_in,
                              void* d_out, int out_size) {
    const float* x     = (const float*)d_in[0];
    const float* gamma = (const float*)d_in[1];
    const float* beta  = (const float*)d_in[2];
    const float* w_qkv = (const float*)d_in[3];
    const float* w_out = (const float*)d_in[4];
    const float* b_out = (const float*)d_in[5];
    float* out = (float*)d_out;

    const int attn_smem = (64 * QST + 4 * 64 * KST) * (int)sizeof(bf16);  // 54272 B
    cudaFuncSetAttribute(attn_kernel, cudaFuncAttributeMaxDynamicSharedMemorySize,
                         attn_smem);

    wconv_kernel<<<1024, 256>>>(w_qkv, w_out);
    gn_kernel<<<BATCH * 32, 256>>>(x, gamma, beta);
    qkv_gemm_kernel<<<dim3(SSP / 128, 3 * CCH / 128, BATCH), 256>>>();
    attn_kernel<<<dim3(SSP / 128, NH, BATCH), 256, attn_smem>>>();
    out_gemm_kernel<<<dim3(SSP / 128, CCH / 128, BATCH), 256>>>(b_out, x, out);
}

// round 9
// speedup vs baseline: 1.1094x; 1.0615x over previous
#include <cuda_runtime.h>
#include <cuda_bf16.h>
#include <cstdint>

#define BATCH 2
#define CCH   512
#define SSP   2304
#define NH    8
#define HD    64
#define CPG   16
#define EPSV  1e-5f
// softmax scale with log2(e) folded in: attention computed in log2 domain
#define QSC   (0.044194173824159216f * 1.4426950408889634f)

typedef __nv_bfloat16 bf16;

// Scratch (allocation-free rule: __device__ globals) — bf16 intermediates
__device__ bf16 g_norm[BATCH * CCH * SSP];
__device__ bf16 g_qkv [BATCH * 3 * CCH * SSP];
__device__ bf16 g_att [BATCH * CCH * SSP];
__device__ bf16 g_wqb [3 * CCH * CCH];
__device__ bf16 g_wob [CCH * CCH];

// ---------------------------------------------------------------------------
// PTX helpers
// ---------------------------------------------------------------------------
__device__ __forceinline__ unsigned sptr(const void* p) {
    return (unsigned)__cvta_generic_to_shared(p);
}
__device__ __forceinline__ void ldsm_x4(unsigned r[4], unsigned a) {
    asm volatile("ldmatrix.sync.aligned.m8n8.x4.shared.b16 {%0,%1,%2,%3}, [%4];"
                 : "=r"(r[0]), "=r"(r[1]), "=r"(r[2]), "=r"(r[3]) : "r"(a));
}
__device__ __forceinline__ void ldsm_x4t(unsigned r[4], unsigned a) {
    asm volatile("ldmatrix.sync.aligned.m8n8.x4.trans.shared.b16 {%0,%1,%2,%3}, [%4];"
                 : "=r"(r[0]), "=r"(r[1]), "=r"(r[2]), "=r"(r[3]) : "r"(a));
}
__device__ __forceinline__ void mma_bf16(float d[4], const unsigned a[4],
                                         const unsigned b[2], const float c[4]) {
    asm volatile(
        "mma.sync.aligned.m16n8k16.row.col.f32.bf16.bf16.f32 "
        "{%0,%1,%2,%3}, {%4,%5,%6,%7}, {%8,%9}, {%10,%11,%12,%13};\n"
        : "=f"(d[0]), "=f"(d[1]), "=f"(d[2]), "=f"(d[3])
        : "r"(a[0]), "r"(a[1]), "r"(a[2]), "r"(a[3]), "r"(b[0]), "r"(b[1]),
          "f"(c[0]), "f"(c[1]), "f"(c[2]), "f"(c[3]));
}
__device__ __forceinline__ float ex2(float x) {
    float y;
    asm("ex2.approx.f32 %0, %1;" : "=f"(y) : "f"(x));
    return y;
}
// pack two f32 -> bf16x2 register (lo = a, hi = b)
__device__ __forceinline__ unsigned pk2(float a, float b) {
    unsigned d;
    asm("cvt.rn.bf16x2.f32 %0, %1, %2;" : "=r"(d) : "f"(b), "f"(a));
    return d;
}
#define CP16(dst, src) \
    asm volatile("cp.async.cg.shared.global [%0], [%1], 16;" :: "r"(dst), "l"(src) : "memory")
#define CP_COMMIT() asm volatile("cp.async.commit_group;" ::: "memory")
#define CP_WAIT1()  asm volatile("cp.async.wait_group 1;" ::: "memory")
#define CP_WAIT0()  asm volatile("cp.async.wait_group 0;" ::: "memory")

__device__ __forceinline__ bf16 tob(float f) { return __float2bfloat16_rn(f); }

// ---------------------------------------------------------------------------
// Weight conversion fp32 -> bf16
// ---------------------------------------------------------------------------
__global__ void wconv_kernel(const float* __restrict__ wq,
                             const float* __restrict__ wo) {
    int t = blockIdx.x * 256 + threadIdx.x;
    const int n1 = 3 * CCH * CCH / 4;
    const int n2 = CCH * CCH / 4;
    if (t < n1) {
        float4 v = ((const float4*)wq)[t];
        bf16* o = g_wqb + t * 4;
        o[0] = tob(v.x); o[1] = tob(v.y); o[2] = tob(v.z); o[3] = tob(v.w);
    } else if (t < n1 + n2) {
        int u = t - n1;
        float4 v = ((const float4*)wo)[u];
        bf16* o = g_wob + u * 4;
        o[0] = tob(v.x); o[1] = tob(v.y); o[2] = tob(v.z); o[3] = tob(v.w);
    }
}

// ---------------------------------------------------------------------------
// GroupNorm -> bf16
// ---------------------------------------------------------------------------
__global__ void gn_kernel(const float* __restrict__ x,
                          const float* __restrict__ gamma,
                          const float* __restrict__ beta) {
    int b = blockIdx.x >> 5;
    int g = blockIdx.x & 31;
    const float4* xp = (const float4*)(x + (size_t)(b * CCH + g * CPG) * SSP);
    bf16* op = g_norm + (size_t)(b * CCH + g * CPG) * SSP;
    int tid = threadIdx.x;
    const int n4 = CPG * SSP / 4;  // 9216

    float s0 = 0.f, s1 = 0.f;
    for (int i = tid; i < n4; i += 256) {
        float4 v = xp[i];
        s0 += v.x + v.y + v.z + v.w;
        s1 += v.x * v.x + v.y * v.y + v.z * v.z + v.w * v.w;
    }
#pragma unroll
    for (int o = 16; o > 0; o >>= 1) {
        s0 += __shfl_xor_sync(0xffffffffu, s0, o);
        s1 += __shfl_xor_sync(0xffffffffu, s1, o);
    }
    __shared__ float sm0[8], sm1[8], stat[2];
    int w = tid >> 5;
    if ((tid & 31) == 0) { sm0[w] = s0; sm1[w] = s1; }
    __syncthreads();
    if (tid == 0) {
        float a = 0.f, q = 0.f;
#pragma unroll
        for (int i = 0; i < 8; i++) { a += sm0[i]; q += sm1[i]; }
        float mean = a * (1.f / 36864.f);
        float var  = q * (1.f / 36864.f) - mean * mean;
        stat[0] = mean;
        stat[1] = rsqrtf(var + EPSV);
    }
    __syncthreads();
    float mean = stat[0], rstd = stat[1];
    for (int i = tid; i < n4; i += 256) {
        int c = g * CPG + i / 576;
        float ga = gamma[c] * rstd;
        float be = beta[c] - mean * ga;
        float4 v = xp[i];
        bf16 o4[4];
        o4[0] = tob(v.x * ga + be); o4[1] = tob(v.y * ga + be);
        o4[2] = tob(v.z * ga + be); o4[3] = tob(v.w * ga + be);
        *(uint2*)(op + i * 4) = *(uint2*)o4;
    }
}

// ---------------------------------------------------------------------------
// bf16 tensor-core GEMM: C[M,N] = A[M,K] @ B[K,N]. 128x128 tile, ktile 32,
// 256 thr = 8 warps (2Mx4N), warp 64x32. cp.async 2-stage double buffer.
// ---------------------------------------------------------------------------
#define AST 40
#define BST 136

__device__ __forceinline__ void gemm_core(
    int M, int N, int K,
    const bf16* __restrict__ A, const bf16* __restrict__ Bp,
    bf16* __restrict__ Cb, float* __restrict__ Cf,
    const float* __restrict__ bias, const float* __restrict__ res,
    bool qscale) {
    __shared__ bf16 As[2][128 * AST];
    __shared__ bf16 Bs[2][32 * BST];
    int tid = threadIdx.x;
    int lane = tid & 31, wid = tid >> 5;
    int wm = (wid >> 2) * 64, wn = (wid & 3) * 32;
    int m0 = blockIdx.y * 128, n0 = blockIdx.x * 128;
    int r0 = lane >> 2, c2 = lane & 3;

    int lm = tid >> 2, lko = (tid & 3) * 8;
    int lk = tid >> 4, lno = (tid & 15) * 8;

    const bf16* Ag = A + (size_t)(m0 + lm) * K + lko;
    const bf16* Bg = Bp + (size_t)lk * N + n0 + lno;

    int a_m = ((lane >> 3) & 1) * 8 + (lane & 7);
    int a_k = ((lane >> 4) & 1) * 8;
    int b_k = ((lane >> 3) & 1) * 8 + (lane & 7);
    int b_n = ((lane >> 4) & 1) * 8;

    float acc[4][4][4];
#pragma unroll
    for (int mt = 0; mt < 4; mt++)
#pragma unroll
        for (int nt = 0; nt < 4; nt++)
#pragma unroll
            for (int e = 0; e < 4; e++) acc[mt][nt][e] = 0.f;

    int nkt = K >> 5;
#pragma unroll
    for (int r = 0; r < 2; r++) {
        CP16(sptr(&As[0][(lm + r * 64) * AST + lko]), Ag + (size_t)r * 64 * K);
        CP16(sptr(&Bs[0][(lk + r * 16) * BST + lno]), Bg + (size_t)r * 16 * N);
    }
    CP_COMMIT();

    for (int kt = 0; kt < nkt; kt++) {
        int buf = kt & 1;
        if (kt + 1 < nkt) {
            int nb = buf ^ 1;
#pragma unroll
            for (int r = 0; r < 2; r++) {
                CP16(sptr(&As[nb][(lm + r * 64) * AST + lko]),
                     Ag + (size_t)(kt + 1) * 32 + (size_t)r * 64 * K);
                CP16(sptr(&Bs[nb][(lk + r * 16) * BST + lno]),
                     Bg + (size_t)((kt + 1) * 32 + r * 16) * N);
            }
            CP_COMMIT();
            CP_WAIT1();
        } else {
            CP_WAIT0();
        }
        __syncthreads();

#pragma unroll
        for (int ks = 0; ks < 2; ks++) {
            unsigned af[4][4], bf_[2][4];
#pragma unroll
            for (int mt = 0; mt < 4; mt++)
                ldsm_x4(af[mt], sptr(&As[buf][(wm + mt * 16 + a_m) * AST + ks * 16 + a_k]));
#pragma unroll
            for (int ng = 0; ng < 2; ng++)
                ldsm_x4t(bf_[ng], sptr(&Bs[buf][(ks * 16 + b_k) * BST + wn + ng * 16 + b_n]));
#pragma unroll
            for (int mt = 0; mt < 4; mt++)
#pragma unroll
                for (int nt = 0; nt < 4; nt++)
                    mma_bf16(acc[mt][nt], af[mt], &bf_[nt >> 1][(nt & 1) * 2], acc[mt][nt]);
        }
        __syncthreads();
    }

#pragma unroll
    for (int mt = 0; mt < 4; mt++) {
        int mA = m0 + wm + mt * 16 + r0;
        float f0 = 1.f, f1 = 1.f;
        if (qscale) {
            f0 = ((mA % 192) < 64) ? QSC : 1.f;
            f1 = (((mA + 8) % 192) < 64) ? QSC : 1.f;
        }
#pragma unroll
        for (int nt = 0; nt < 4; nt++) {
            int n = n0 + wn + nt * 8 + 2 * c2;
            if (Cb) {
                unsigned p0 = pk2(acc[mt][nt][0] * f0, acc[mt][nt][1] * f0);
                unsigned p1 = pk2(acc[mt][nt][2] * f1, acc[mt][nt][3] * f1);
                *(unsigned*)(Cb + (size_t)mA * N + n) = p0;
                *(unsigned*)(Cb + (size_t)(mA + 8) * N + n) = p1;
            } else {
                float bv0 = bias[mA], bv1 = bias[mA + 8];
                float2 o0, o1;
                o0.x = acc[mt][nt][0] + bv0; o0.y = acc[mt][nt][1] + bv0;
                o1.x = acc[mt][nt][2] + bv1; o1.y = acc[mt][nt][3] + bv1;
                float2 q0v = *(const float2*)(res + (size_t)mA * N + n);
                float2 q1v = *(const float2*)(res + (size_t)(mA + 8) * N + n);
                o0.x += q0v.x; o0.y += q0v.y; o1.x += q1v.x; o1.y += q1v.y;
                *(float2*)(Cf + (size_t)mA * N + n) = o0;
                *(float2*)(Cf + (size_t)(mA + 8) * N + n) = o1;
            }
        }
    }
}

__global__ void __launch_bounds__(256, 2) qkv_gemm_kernel() {
    int b = blockIdx.z;
    gemm_core(3 * CCH, SSP, CCH, g_wqb,
              g_norm + (size_t)b * CCH * SSP,
              g_qkv + (size_t)b * 3 * CCH * SSP, nullptr,
              nullptr, nullptr, true);
}

__global__ void __launch_bounds__(256, 2) out_gemm_kernel(const float* __restrict__ b_out,
                                                          const float* __restrict__ x,
                                                          float* __restrict__ out) {
    int b = blockIdx.z;
    gemm_core(CCH, SSP, CCH, g_wob,
              g_att + (size_t)b * CCH * SSP,
              nullptr, out + (size_t)b * CCH * SSP,
              b_out, x + (size_t)b * CCH * SSP, false);
}

// ---------------------------------------------------------------------------
// Flash attention bf16, log2-domain softmax, P in registers.
// Block = 256 queries of one (b,h), 256 threads = 8 warps; each warp owns
// 32 queries (two m16 fragments) so K/V ldmatrix fragments are reused 2x.
// Grid 9x8x2 = 144 CTAs = one wave at 1 CTA/SM.
// ---------------------------------------------------------------------------
#define QST 264
#define KST 72
#define NT_TILES (SSP / 64)

__global__ void __launch_bounds__(256, 1) attn_kernel() {
    extern __shared__ bf16 smn[];
    bf16* Qs = smn;                       // 64 x 264
    bf16* Ks = Qs + 64 * QST;             // 2 x 64 x 72
    bf16* Vs = Ks + 2 * 64 * KST;         // 2 x 64 x 72

    int tid = threadIdx.x, lane = tid & 31, w = tid >> 5;
    int r0 = lane >> 2, c2 = lane & 3;
    int wm = w * 32;
    int h = blockIdx.y, b = blockIdx.z;
    int q0 = blockIdx.x * 256;
    const bf16* qp = g_qkv + ((size_t)b * 3 * CCH + h * 3 * HD) * SSP;
    const bf16* kp = qp + (size_t)HD * SSP;
    const bf16* vp = qp + (size_t)2 * HD * SSP;

    int t8  = (lane >> 3) & 1, t16 = (lane >> 4) & 1, t7 = lane & 7;

    // Load Q tile [d=64][i=256]
    {
        int io = (tid & 31) * 8, d0 = tid >> 5;
#pragma unroll
        for (int r = 0; r < 8; r++) {
            int d = d0 + 8 * r;
            *(uint4*)(Qs + d * QST + io) =
                *(const uint4*)(qp + (size_t)d * SSP + q0 + io);
        }
    }

    int ld = tid >> 3, ljo = (tid & 7) * 8;
#pragma unroll
    for (int r = 0; r < 2; r++) {
        CP16(sptr(Ks + (ld + 32 * r) * KST + ljo), kp + (size_t)(ld + 32 * r) * SSP + ljo);
        CP16(sptr(Vs + (ld + 32 * r) * KST + ljo), vp + (size_t)(ld + 32 * r) * SSP + ljo);
    }
    CP_COMMIT();

    // per-warp state: 2 m-frags x 2 row-groups
    float m_run[4] = {-1e30f, -1e30f, -1e30f, -1e30f};
    float l_par[4] = {0.f, 0.f, 0.f, 0.f};
    float o[2][8][4];
#pragma unroll
    for (int mq = 0; mq < 2; mq++)
#pragma unroll
        for (int nt = 0; nt < 8; nt++)
#pragma unroll
            for (int e = 0; e < 4; e++) o[mq][nt][e] = 0.f;

    for (int t = 0; t < NT_TILES; t++) {
        int buf = t & 1;
        if (t + 1 < NT_TILES) {
            int nb = buf ^ 1;
            int t0n = (t + 1) * 64;
#pragma unroll
            for (int r = 0; r < 2; r++) {
                CP16(sptr(Ks + (nb * 64 + ld + 32 * r) * KST + ljo),
                     kp + (size_t)(ld + 32 * r) * SSP + t0n + ljo);
                CP16(sptr(Vs + (nb * 64 + ld + 32 * r) * KST + ljo),
                     vp + (size_t)(ld + 32 * r) * SSP + t0n + ljo);
            }
            CP_COMMIT();
            CP_WAIT1();
        } else {
            CP_WAIT0();
        }
        __syncthreads();

        // ---- S = Q^T K for both m-fragments; K frags loaded once
        float s[2][8][4];
#pragma unroll
        for (int mq = 0; mq < 2; mq++)
#pragma unroll
            for (int nt = 0; nt < 8; nt++)
#pragma unroll
                for (int e = 0; e < 4; e++) s[mq][nt][e] = 0.f;
        const bf16* Kb = Ks + buf * 64 * KST;
#pragma unroll
        for (int ks = 0; ks < 4; ks++) {
            unsigned a0[4], a1[4], bb[4][4];
            ldsm_x4t(a0, sptr(Qs + (ks * 16 + t16 * 8 + t7) * QST + wm + t8 * 8));
            ldsm_x4t(a1, sptr(Qs + (ks * 16 + t16 * 8 + t7) * QST + wm + 16 + t8 * 8));
#pragma unroll
            for (int ng = 0; ng < 4; ng++)
                ldsm_x4t(bb[ng], sptr(Kb + (ks * 16 + t8 * 8 + t7) * KST + ng * 16 + t16 * 8));
#pragma unroll
            for (int nt = 0; nt < 8; nt++) {
                mma_bf16(s[0][nt], a0, &bb[nt >> 1][(nt & 1) * 2], s[0][nt]);
                mma_bf16(s[1][nt], a1, &bb[nt >> 1][(nt & 1) * 2], s[1][nt]);
            }
        }

        // ---- online softmax per m-fragment (quad reduction)
        float mn[4], cr[4];
#pragma unroll
        for (int mq = 0; mq < 2; mq++) {
            float mx0 = -1e30f, mx1 = -1e30f;
#pragma unroll
            for (int nt = 0; nt < 8; nt++) {
                mx0 = fmaxf(mx0, fmaxf(s[mq][nt][0], s[mq][nt][1]));
                mx1 = fmaxf(mx1, fmaxf(s[mq][nt][2], s[mq][nt][3]));
            }
#pragma unroll
            for (int off = 1; off <= 2; off <<= 1) {
                mx0 = fmaxf(mx0, __shfl_xor_sync(0xffffffffu, mx0, off));
                mx1 = fmaxf(mx1, __shfl_xor_sync(0xffffffffu, mx1, off));
            }
            float mn0 = fmaxf(m_run[2 * mq], mx0);
            float mn1 = fmaxf(m_run[2 * mq + 1], mx1);
            cr[2 * mq]     = ex2(m_run[2 * mq] - mn0);
            cr[2 * mq + 1] = ex2(m_run[2 * mq + 1] - mn1);
            m_run[2 * mq] = mn0; m_run[2 * mq + 1] = mn1;
            mn[2 * mq] = mn0; mn[2 * mq + 1] = mn1;
#pragma unroll
            for (int nt = 0; nt < 8; nt++) {
                o[mq][nt][0] *= cr[2 * mq];     o[mq][nt][1] *= cr[2 * mq];
                o[mq][nt][2] *= cr[2 * mq + 1]; o[mq][nt][3] *= cr[2 * mq + 1];
            }
        }

        // ---- exp2 in regs, pack P fragments, PV mma; V frags shared by mq
        float sum[4] = {0.f, 0.f, 0.f, 0.f};
        const bf16* Vb = Vs + buf * 64 * KST;
#pragma unroll
        for (int ks = 0; ks < 4; ks++) {
            unsigned bb[4][4];
#pragma unroll
            for (int ng = 0; ng < 4; ng++)
                ldsm_x4(bb[ng], sptr(Vb + (ng * 16 + t16 * 8 + t7) * KST + ks * 16 + t8 * 8));
#pragma unroll
            for (int mq = 0; mq < 2; mq++) {
                int n0i = 2 * ks, n1i = 2 * ks + 1;
                float e00 = ex2(s[mq][n0i][0] - mn[2 * mq]);
                float e01 = ex2(s[mq][n0i][1] - mn[2 * mq]);
                float e02 = ex2(s[mq][n0i][2] - mn[2 * mq + 1]);
                float e03 = ex2(s[mq][n0i][3] - mn[2 * mq + 1]);
                float e10 = ex2(s[mq][n1i][0] - mn[2 * mq]);
                float e11 = ex2(s[mq][n1i][1] - mn[2 * mq]);
                float e12 = ex2(s[mq][n1i][2] - mn[2 * mq + 1]);
                float e13 = ex2(s[mq][n1i][3] - mn[2 * mq + 1]);
                sum[2 * mq]     += e00 + e01 + e10 + e11;
                sum[2 * mq + 1] += e02 + e03 + e12 + e13;
                unsigned a[4];
                a[0] = pk2(e00, e01);
                a[1] = pk2(e02, e03);
                a[2] = pk2(e10, e11);
                a[3] = pk2(e12, e13);
#pragma unroll
                for (int nd = 0; nd < 8; nd++)
                    mma_bf16(o[mq][nd], a, &bb[nd >> 1][(nd & 1) * 2], o[mq][nd]);
            }
        }
#pragma unroll
        for (int j = 0; j < 4; j++) l_par[j] = l_par[j] * cr[j] + sum[j];
        __syncthreads();
    }

    // ---- final l reduction across quad, then finalize
    float inv[4];
#pragma unroll
    for (int j = 0; j < 4; j++) {
        float l = l_par[j];
#pragma unroll
        for (int off = 1; off <= 2; off <<= 1)
            l += __shfl_xor_sync(0xffffffffu, l, off);
        inv[j] = 1.f / l;
    }
    __syncthreads();
    bf16* Os = Qs;  // reuse staging, [dd][i] stride QST
#pragma unroll
    for (int mq = 0; mq < 2; mq++)
#pragma unroll
        for (int nt = 0; nt < 8; nt++) {
            int dd = nt * 8 + 2 * c2;
            int ib = wm + mq * 16 + r0;
            Os[dd * QST + ib]           = tob(o[mq][nt][0] * inv[2 * mq]);
            Os[(dd + 1) * QST + ib]     = tob(o[mq][nt][1] * inv[2 * mq]);
            Os[dd * QST + ib + 8]       = tob(o[mq][nt][2] * inv[2 * mq + 1]);
            Os[(dd + 1) * QST + ib + 8] = tob(o[mq][nt][3] * inv[2 * mq + 1]);
        }
    __syncthreads();
    bf16* ap = g_att + ((size_t)b * CCH + h * HD) * SSP;
    {
        int io = (tid & 31) * 8, d0 = tid >> 5;
#pragma unroll
        for (int r = 0; r < 8; r++) {
            int d = d0 + 8 * r;
            *(uint4*)(ap + (size_t)d * SSP + q0 + io) = *(uint4*)(Os + d * QST + io);
        }
    }
}

// ---------------------------------------------------------------------------
extern "C" void kernel_launch(void* const* d_in, const int* in_sizes, int n_in,
                              void* d_out, int out_size) {
    const float* x     = (const float*)d_in[0];
    const float* gamma = (const float*)d_in[1];
    const float* beta  = (const float*)d_in[2];
    const float* w_qkv = (const float*)d_in[3];
    const float* w_out = (const float*)d_in[4];
    const float* b_out = (const float*)d_in[5];
    float* out = (float*)d_out;

    const int attn_smem = (64 * QST + 4 * 64 * KST) * (int)sizeof(bf16);  // 70656 B
    cudaFuncSetAttribute(attn_kernel, cudaFuncAttributeMaxDynamicSharedMemorySize,
                         attn_smem);

    wconv_kernel<<<1024, 256>>>(w_qkv, w_out);
    gn_kernel<<<BATCH * 32, 256>>>(x, gamma, beta);
    qkv_gemm_kernel<<<dim3(SSP / 128, 3 * CCH / 128, BATCH), 256>>>();
    attn_kernel<<<dim3(SSP / 256, NH, BATCH), 256, attn_smem>>>();
    out_gemm_kernel<<<dim3(SSP / 128, CCH / 128, BATCH), 256>>>(b_out, x, out);
}